// round 14
// baseline (speedup 1.0000x reference)
#include <cuda_runtime.h>
#include <cuda_fp16.h>
#include <math.h>
#include <stdint.h>

#define NN 50000
#define EMAX 800000
#define AGG_BLKS 6250  // NN/8 warps-per-block

// ======================= device scratch (triplicated per graph) ==========
__device__ float g_dis[3][NN];
__device__ int   g_count[3][NN];
__device__ int   g_fill[3][NN];
__device__ int   g_rowptr[3][NN + 1];
__device__ int   g_bsum[3][256];
__device__ int   g_boff[3][256];
__device__ int   g_csrc[3][EMAX];
__device__ float g_cw[3][EMAX];
__device__ __half g_h[3][(size_t)NN * 256];   // GEMM output
__device__ __half g_a[3][(size_t)NN * 256];   // agg output / GEMM input
__device__ __half g_Wt1[256 * 256];           // W^T fp16 [N,K]
__device__ __half g_Wt2[128 * 256];
__device__ __half g_Wt3[64 * 128];
__device__ float g_part[3 * AGG_BLKS];        // layer-3 block partials

// ======================= PTX wrappers =======================
__device__ __forceinline__ uint32_t smem_u32(const void* p) {
    uint32_t a;
    asm("{ .reg .u64 t; cvta.to.shared.u64 t, %1; cvt.u32.u64 %0, t; }"
        : "=r"(a) : "l"(p));
    return a;
}

__device__ __forceinline__ void ldsm_x4(uint32_t* r, uint32_t addr) {
    asm volatile(
        "ldmatrix.sync.aligned.m8n8.x4.shared.b16 {%0,%1,%2,%3}, [%4];"
        : "=r"(r[0]), "=r"(r[1]), "=r"(r[2]), "=r"(r[3]) : "r"(addr));
}

__device__ __forceinline__ void mma_f16(float* d, const uint32_t* a,
                                        uint32_t b0, uint32_t b1) {
    asm volatile(
        "mma.sync.aligned.m16n8k16.row.col.f32.f16.f16.f32 "
        "{%0,%1,%2,%3}, {%4,%5,%6,%7}, {%8,%9}, {%0,%1,%2,%3};"
        : "+f"(d[0]), "+f"(d[1]), "+f"(d[2]), "+f"(d[3])
        : "r"(a[0]), "r"(a[1]), "r"(a[2]), "r"(a[3]), "r"(b0), "r"(b1));
}

__device__ __forceinline__ float2 h2f2(uint32_t u) {
    return __half22float2(*(__half2*)&u);
}
__device__ __forceinline__ uint32_t f2h2(float x, float y) {
    __half2 h = __floats2half2_rn(x, y);
    return *(uint32_t*)&h;
}

// ======================= graph-prep kernels ==============================
__global__ void count_init_kernel(int z) {
    int i = blockIdx.x * blockDim.x + threadIdx.x;
    if (i < NN) { g_count[z][i] = 0; g_fill[z][i] = 0; }
}

__global__ void count_edges_kernel(int z, const int* __restrict__ ei, int E) {
    int e = blockIdx.x * blockDim.x + threadIdx.x;
    const int* dst = ei + E;
    if (e < E) atomicAdd(&g_count[z][dst[e]], 1);
}

__global__ void scan_block_kernel(int z) {
    __shared__ int sd[256];
    int tid = threadIdx.x;
    int i = blockIdx.x * 256 + tid;
    int v = (i < NN) ? g_count[z][i] : 0;
    if (i < NN) g_dis[z][i] = rsqrtf((float)v + 1.0f);
    sd[tid] = v;
    __syncthreads();
    for (int off = 1; off < 256; off <<= 1) {
        int t = (tid >= off) ? sd[tid - off] : 0;
        __syncthreads();
        sd[tid] += t;
        __syncthreads();
    }
    if (i < NN) g_rowptr[z][i] = sd[tid] - v;
    if (tid == 255) g_bsum[z][blockIdx.x] = sd[255];
}

__global__ void scan_tops_kernel(int z, int nb) {
    __shared__ int sd[256];
    int tid = threadIdx.x;
    int v = (tid < nb) ? g_bsum[z][tid] : 0;
    sd[tid] = v;
    __syncthreads();
    for (int off = 1; off < 256; off <<= 1) {
        int t = (tid >= off) ? sd[tid - off] : 0;
        __syncthreads();
        sd[tid] += t;
        __syncthreads();
    }
    g_boff[z][tid] = sd[tid] - v;
}

__global__ void scan_add_kernel(int z, int E) {
    int i = blockIdx.x * 256 + threadIdx.x;
    if (i < NN) g_rowptr[z][i] += g_boff[z][blockIdx.x];
    if (i == 0) g_rowptr[z][NN] = E;
}

__global__ void fill_csr_kernel(int z, const int* __restrict__ ei, int E) {
    int e = blockIdx.x * blockDim.x + threadIdx.x;
    if (e >= E) return;
    const int* src = ei;
    const int* dst = ei + E;
    int d = dst[e];
    int s = src[e];
    int pos = g_rowptr[z][d] + atomicAdd(&g_fill[z][d], 1);
    g_csrc[z][pos] = s;
    g_cw[z][pos] = g_dis[z][s] * g_dis[z][d];
}

// all three W [K,N] fp32 -> Wt [N,K] fp16 in one launch
__global__ void wt_all_kernel(const float* W1, const float* W2,
                              const float* W3) {
    int i = blockIdx.x * blockDim.x + threadIdx.x;
    if (i < 65536) {
        int nrow = i >> 8, k = i & 255;
        g_Wt1[i] = __float2half_rn(W1[k * 256 + nrow]);
    } else if (i < 98304) {
        int j = i - 65536;
        int nrow = j >> 8, k = j & 255;
        g_Wt2[j] = __float2half_rn(W2[k * 128 + nrow]);
    } else if (i < 106496) {
        int j = i - 98304;
        int nrow = j >> 7, k = j & 127;
        g_Wt3[j] = __float2half_rn(W3[k * 64 + nrow]);
    }
}

// ======================= HMMA GEMM =======================
// C[n,N](fp16) = A[n,K] @ Wt^T. CTA: 128 rows; A staged once; loop over N in
// CN-col chunks (CN = min(N,128)). 8 warps 4x2, warp tile 32 x CN/2.
template <bool AFP32, int K, int N>
__global__ __launch_bounds__(256) void gemm_mma_kernel(
    const void* __restrict__ Ain, const __half* __restrict__ Wt,
    __half* __restrict__ C, int n) {
    constexpr int CN = (N >= 128) ? 128 : N;
    constexpr int LDS = K + 8;
    extern __shared__ __half sm[];
    __half* As = sm;               // [128][LDS]
    __half* Ws = sm + 128 * LDS;   // [CN][LDS]

    int tid = threadIdx.x;
    int lane = tid & 31;
    int warp = tid >> 5;
    int rowBase = blockIdx.x * 128;
    int warpM = (warp >> 1) * 32;
    int warpN = (warp & 1) * (CN / 2);

    // ---- stage A (128 x K) once ----
    {
        constexpr int K8 = K / 8;
        for (int v = tid; v < 128 * K8; v += 256) {
            int r = v / K8;
            int k0 = (v - r * K8) * 8;
            int gr = rowBase + r;
            uint4 val = make_uint4(0, 0, 0, 0);
            if (gr < n) {
                if (AFP32) {
                    const float4* ap =
                        (const float4*)((const float*)Ain + (size_t)gr * K + k0);
                    float4 f0 = ap[0], f1 = ap[1];
                    val.x = f2h2(f0.x, f0.y);
                    val.y = f2h2(f0.z, f0.w);
                    val.z = f2h2(f1.x, f1.y);
                    val.w = f2h2(f1.z, f1.w);
                } else {
                    val = *(const uint4*)((const __half*)Ain +
                                          (size_t)gr * K + k0);
                }
            }
            *(uint4*)(As + r * LDS + k0) = val;
        }
    }
    __syncthreads();

    uint32_t sA = smem_u32(As);
    uint32_t sW = smem_u32(Ws);
    int lr = lane & 15;
    int lc = (lane >> 4) * 8;
    int groupID = lane >> 2;
    int qcol = (lane & 3) * 2;

    for (int cb = 0; cb < N / CN; cb++) {
        int colBase = cb * CN;
        if (cb) __syncthreads();
        // ---- stage W chunk (CN x K) ----
        {
            constexpr int K8 = K / 8;
            for (int v = tid; v < CN * K8; v += 256) {
                int r = v / K8;
                int k0 = (v - r * K8) * 8;
                *(uint4*)(Ws + r * LDS + k0) =
                    *(const uint4*)(Wt + (size_t)(colBase + r) * K + k0);
            }
        }
        __syncthreads();

        float acc[2][CN / 16][4] = {};
#pragma unroll
        for (int k0 = 0; k0 < K; k0 += 16) {
            uint32_t af[2][4], bf[CN / 32][4];
#pragma unroll
            for (int mt = 0; mt < 2; mt++) {
                uint32_t addr =
                    sA + ((warpM + mt * 16 + lr) * LDS + k0 + lc) * 2;
                ldsm_x4(af[mt], addr);
            }
#pragma unroll
            for (int nh = 0; nh < CN / 32; nh++) {
                uint32_t addr =
                    sW + ((warpN + nh * 16 + lr) * LDS + k0 + lc) * 2;
                ldsm_x4(bf[nh], addr);  // Ws is [n][k], k-contiguous
            }
#pragma unroll
            for (int mt = 0; mt < 2; mt++) {
#pragma unroll
                for (int nh = 0; nh < CN / 32; nh++) {
                    mma_f16(acc[mt][nh * 2 + 0], af[mt], bf[nh][0], bf[nh][2]);
                    mma_f16(acc[mt][nh * 2 + 1], af[mt], bf[nh][1], bf[nh][3]);
                }
            }
        }

        // ---- epilogue: acc[mt][idx] covers col warpN + idx*8 ----
#pragma unroll
        for (int mt = 0; mt < 2; mt++) {
#pragma unroll
            for (int half = 0; half < 2; half++) {
                int row = rowBase + warpM + mt * 16 + groupID + half * 8;
                if (row < n) {
                    uint32_t* orow = (uint32_t*)(C + (size_t)row * N + colBase);
#pragma unroll
                    for (int nt = 0; nt < CN / 16; nt++) {
                        orow[(warpN + nt * 8 + qcol) >> 1] =
                            f2h2(acc[mt][nt][half * 2 + 0],
                                 acc[mt][nt][half * 2 + 1]);
                    }
                }
            }
        }
    }
}

// ======================= aggregation (fp16 gather, vectorized) ============
__global__ __launch_bounds__(256) void agg256_kernel(
    int z, const __half* __restrict__ h, const float* __restrict__ bias,
    __half* __restrict__ out) {
    int warp = blockIdx.x * 8 + (threadIdx.x >> 5);
    int lane = threadIdx.x & 31;
    if (warp >= NN) return;

    float dv = g_dis[z][warp];
    float dd = dv * dv;
    float acc[8];
    {
        uint4 u = *(const uint4*)(h + (size_t)warp * 256 + lane * 8);
        float2 f0 = h2f2(u.x), f1 = h2f2(u.y), f2 = h2f2(u.z), f3 = h2f2(u.w);
        const float* bp = bias + lane * 8;
        acc[0] = f0.x * dd + bp[0]; acc[1] = f0.y * dd + bp[1];
        acc[2] = f1.x * dd + bp[2]; acc[3] = f1.y * dd + bp[3];
        acc[4] = f2.x * dd + bp[4]; acc[5] = f2.y * dd + bp[5];
        acc[6] = f3.x * dd + bp[6]; acc[7] = f3.y * dd + bp[7];
    }

    int e0 = g_rowptr[z][warp];
    int e1 = g_rowptr[z][warp + 1];
    int e = e0;
    for (; e + 1 < e1; e += 2) {
        int s0 = g_csrc[z][e], s1 = g_csrc[z][e + 1];
        float w0 = g_cw[z][e], w1 = g_cw[z][e + 1];
        uint4 u0 = __ldg((const uint4*)(h + (size_t)s0 * 256) + lane);
        uint4 u1 = __ldg((const uint4*)(h + (size_t)s1 * 256) + lane);
        float2 a0 = h2f2(u0.x), a1 = h2f2(u0.y), a2 = h2f2(u0.z), a3 = h2f2(u0.w);
        acc[0] = fmaf(w0, a0.x, acc[0]); acc[1] = fmaf(w0, a0.y, acc[1]);
        acc[2] = fmaf(w0, a1.x, acc[2]); acc[3] = fmaf(w0, a1.y, acc[3]);
        acc[4] = fmaf(w0, a2.x, acc[4]); acc[5] = fmaf(w0, a2.y, acc[5]);
        acc[6] = fmaf(w0, a3.x, acc[6]); acc[7] = fmaf(w0, a3.y, acc[7]);
        float2 b0 = h2f2(u1.x), b1 = h2f2(u1.y), b2 = h2f2(u1.z), b3 = h2f2(u1.w);
        acc[0] = fmaf(w1, b0.x, acc[0]); acc[1] = fmaf(w1, b0.y, acc[1]);
        acc[2] = fmaf(w1, b1.x, acc[2]); acc[3] = fmaf(w1, b1.y, acc[3]);
        acc[4] = fmaf(w1, b2.x, acc[4]); acc[5] = fmaf(w1, b2.y, acc[5]);
        acc[6] = fmaf(w1, b3.x, acc[6]); acc[7] = fmaf(w1, b3.y, acc[7]);
    }
    if (e < e1) {
        int s0 = g_csrc[z][e];
        float w0 = g_cw[z][e];
        uint4 u0 = __ldg((const uint4*)(h + (size_t)s0 * 256) + lane);
        float2 a0 = h2f2(u0.x), a1 = h2f2(u0.y), a2 = h2f2(u0.z), a3 = h2f2(u0.w);
        acc[0] = fmaf(w0, a0.x, acc[0]); acc[1] = fmaf(w0, a0.y, acc[1]);
        acc[2] = fmaf(w0, a1.x, acc[2]); acc[3] = fmaf(w0, a1.y, acc[3]);
        acc[4] = fmaf(w0, a2.x, acc[4]); acc[5] = fmaf(w0, a2.y, acc[5]);
        acc[6] = fmaf(w0, a3.x, acc[6]); acc[7] = fmaf(w0, a3.y, acc[7]);
    }

    uint4 o;
    o.x = f2h2(fmaxf(acc[0], 0.f), fmaxf(acc[1], 0.f));
    o.y = f2h2(fmaxf(acc[2], 0.f), fmaxf(acc[3], 0.f));
    o.z = f2h2(fmaxf(acc[4], 0.f), fmaxf(acc[5], 0.f));
    o.w = f2h2(fmaxf(acc[6], 0.f), fmaxf(acc[7], 0.f));
    *((uint4*)(out + (size_t)warp * 256) + lane) = o;
}

__global__ __launch_bounds__(256) void agg128_kernel(
    int z, const __half* __restrict__ h, const float* __restrict__ bias,
    __half* __restrict__ out) {
    int warp = blockIdx.x * 8 + (threadIdx.x >> 5);
    int lane = threadIdx.x & 31;
    if (warp >= NN) return;

    float dv = g_dis[z][warp];
    float dd = dv * dv;
    float acc[4];
    {
        uint2 u = *(const uint2*)(h + (size_t)warp * 128 + lane * 4);
        float2 f0 = h2f2(u.x), f1 = h2f2(u.y);
        const float* bp = bias + lane * 4;
        acc[0] = f0.x * dd + bp[0]; acc[1] = f0.y * dd + bp[1];
        acc[2] = f1.x * dd + bp[2]; acc[3] = f1.y * dd + bp[3];
    }

    int e0 = g_rowptr[z][warp];
    int e1 = g_rowptr[z][warp + 1];
    int e = e0;
    for (; e + 1 < e1; e += 2) {
        int s0 = g_csrc[z][e], s1 = g_csrc[z][e + 1];
        float w0 = g_cw[z][e], w1 = g_cw[z][e + 1];
        uint2 u0 = __ldg((const uint2*)(h + (size_t)s0 * 128) + lane);
        uint2 u1 = __ldg((const uint2*)(h + (size_t)s1 * 128) + lane);
        float2 a0 = h2f2(u0.x), a1 = h2f2(u0.y);
        acc[0] = fmaf(w0, a0.x, acc[0]); acc[1] = fmaf(w0, a0.y, acc[1]);
        acc[2] = fmaf(w0, a1.x, acc[2]); acc[3] = fmaf(w0, a1.y, acc[3]);
        float2 b0 = h2f2(u1.x), b1 = h2f2(u1.y);
        acc[0] = fmaf(w1, b0.x, acc[0]); acc[1] = fmaf(w1, b0.y, acc[1]);
        acc[2] = fmaf(w1, b1.x, acc[2]); acc[3] = fmaf(w1, b1.y, acc[3]);
    }
    if (e < e1) {
        int s0 = g_csrc[z][e];
        float w0 = g_cw[z][e];
        uint2 u0 = __ldg((const uint2*)(h + (size_t)s0 * 128) + lane);
        float2 a0 = h2f2(u0.x), a1 = h2f2(u0.y);
        acc[0] = fmaf(w0, a0.x, acc[0]); acc[1] = fmaf(w0, a0.y, acc[1]);
        acc[2] = fmaf(w0, a1.x, acc[2]); acc[3] = fmaf(w0, a1.y, acc[3]);
    }

    uint2 o;
    o.x = f2h2(fmaxf(acc[0], 0.f), fmaxf(acc[1], 0.f));
    o.y = f2h2(fmaxf(acc[2], 0.f), fmaxf(acc[3], 0.f));
    *((uint2*)(out + (size_t)warp * 128) + lane) = o;
}

// layer-3 agg (M=64) fused with relu + block partial sum (fp32 path)
__global__ __launch_bounds__(256) void agg3_kernel(
    int z, const __half* __restrict__ h, const float* __restrict__ bias) {
    int wlocal = threadIdx.x >> 5;
    int warp = blockIdx.x * 8 + wlocal;
    int lane = threadIdx.x & 31;

    float s = 0.0f;
    if (warp < NN) {
        float dv = g_dis[z][warp];
        float dd = dv * dv;
        uint32_t u = *((const uint32_t*)(h + (size_t)warp * 64) + lane);
        float2 f = h2f2(u);
        int c = 2 * lane;
        float a0 = f.x * dd + bias[c];
        float a1 = f.y * dd + bias[c + 1];

        int e0 = g_rowptr[z][warp];
        int e1 = g_rowptr[z][warp + 1];
        int e = e0;
        for (; e + 1 < e1; e += 2) {
            int s0 = g_csrc[z][e], s1 = g_csrc[z][e + 1];
            float w0 = g_cw[z][e], w1 = g_cw[z][e + 1];
            uint32_t u0 = __ldg((const uint32_t*)(h + (size_t)s0 * 64) + lane);
            uint32_t u1 = __ldg((const uint32_t*)(h + (size_t)s1 * 64) + lane);
            float2 fa = h2f2(u0), fb = h2f2(u1);
            a0 = fmaf(w0, fa.x, a0); a1 = fmaf(w0, fa.y, a1);
            a0 = fmaf(w1, fb.x, a0); a1 = fmaf(w1, fb.y, a1);
        }
        if (e < e1) {
            int s0 = g_csrc[z][e];
            float w0 = g_cw[z][e];
            uint32_t u0 = __ldg((const uint32_t*)(h + (size_t)s0 * 64) + lane);
            float2 fa = h2f2(u0);
            a0 = fmaf(w0, fa.x, a0); a1 = fmaf(w0, fa.y, a1);
        }
        s = fmaxf(a0, 0.0f) + fmaxf(a1, 0.0f);
    }
#pragma unroll
    for (int o = 16; o; o >>= 1) s += __shfl_down_sync(0xFFFFFFFFu, s, o);
    __shared__ float ws[8];
    if (lane == 0) ws[wlocal] = s;
    __syncthreads();
    if (threadIdx.x < 8) {
        float t = ws[threadIdx.x];
#pragma unroll
        for (int o = 4; o; o >>= 1) t += __shfl_down_sync(0xFFu, t, o);
        if (threadIdx.x == 0) g_part[z * AGG_BLKS + blockIdx.x] = t;
    }
}

__global__ void final_reduce_kernel(float* __restrict__ out) {
    float s = 0.0f;
    for (int i = threadIdx.x; i < 3 * AGG_BLKS; i += 1024) s += g_part[i];
#pragma unroll
    for (int o = 16; o; o >>= 1) s += __shfl_down_sync(0xFFFFFFFFu, s, o);
    __shared__ float ws[32];
    if ((threadIdx.x & 31) == 0) ws[threadIdx.x >> 5] = s;
    __syncthreads();
    if (threadIdx.x < 32) {
        float t = ws[threadIdx.x];
#pragma unroll
        for (int o = 16; o; o >>= 1) t += __shfl_down_sync(0xFFFFFFFFu, t, o);
        if (threadIdx.x == 0) out[0] = t * (1.0f / 64.0f);
    }
}

// ======================= launcher =======================
extern "C" void kernel_launch(void* const* d_in, const int* in_sizes, int n_in,
                              void* d_out, int out_size) {
    float* out = (float*)d_out;

    // one-time host resources: EXACTLY 3 streams (R11-proven footprint)
    static cudaStream_t st[3];
    static cudaEvent_t evW, evPrep[3], evJoin[3];
    static bool inited = false;
    if (!inited) {
        inited = true;
        for (int g = 0; g < 3; g++) {
            cudaStreamCreateWithFlags(&st[g], cudaStreamNonBlocking);
            cudaEventCreateWithFlags(&evPrep[g], cudaEventDisableTiming);
            cudaEventCreateWithFlags(&evJoin[g], cudaEventDisableTiming);
        }
        cudaEventCreateWithFlags(&evW, cudaEventDisableTiming);
    }

    __half *ph, *pa, *pw1, *pw2, *pw3;
    cudaGetSymbolAddress((void**)&ph, g_h);
    cudaGetSymbolAddress((void**)&pa, g_a);
    cudaGetSymbolAddress((void**)&pw1, g_Wt1);
    cudaGetSymbolAddress((void**)&pw2, g_Wt2);
    cudaGetSymbolAddress((void**)&pw3, g_Wt3);

    const int SM_L12 = (128 + 128) * (256 + 8) * 2;  // 135168
    const int SM_L3  = (128 + 64) * (128 + 8) * 2;   // 52224
    cudaFuncSetAttribute(gemm_mma_kernel<true, 256, 256>,
                         cudaFuncAttributeMaxDynamicSharedMemorySize, SM_L12);
    cudaFuncSetAttribute(gemm_mma_kernel<false, 256, 128>,
                         cudaFuncAttributeMaxDynamicSharedMemorySize, SM_L12);
    cudaFuncSetAttribute(gemm_mma_kernel<false, 128, 64>,
                         cudaFuncAttributeMaxDynamicSharedMemorySize, SM_L3);

    const int NB = (NN + 255) / 256;  // 196
    const int GB = (NN + 127) / 128;  // 391

    const float* b1 = (const float*)d_in[7];
    const float* b2 = (const float*)d_in[9];
    const float* b3 = (const float*)d_in[11];

    // weights first on default stream, then serialized prep chains
    wt_all_kernel<<<(106496 + 255) / 256, 256>>>(
        (const float*)d_in[6], (const float*)d_in[8], (const float*)d_in[10]);
    cudaEventRecord(evW, 0);

    for (int g = 0; g < 3; g++) {
        const int* ei = (const int*)d_in[3 + g];
        int E = in_sizes[3 + g] / 2;
        int EB = (E + 255) / 256;
        count_init_kernel<<<NB, 256>>>(g);
        count_edges_kernel<<<EB, 256>>>(g, ei, E);
        scan_block_kernel<<<NB, 256>>>(g);
        scan_tops_kernel<<<1, 256>>>(g, NB);
        scan_add_kernel<<<NB, 256>>>(g, E);
        fill_csr_kernel<<<EB, 256>>>(g, ei, E);
        cudaEventRecord(evPrep[g], 0);
    }

    for (int g = 0; g < 3; g++) {
        __half* hg = ph + (size_t)g * NN * 256;
        __half* ag = pa + (size_t)g * NN * 256;
        cudaStream_t s = st[g];

        // gemm1 needs only weights; overlaps the prep chains above
        cudaStreamWaitEvent(s, evW, 0);
        gemm_mma_kernel<true, 256, 256>
            <<<GB, 256, SM_L12, s>>>(d_in[g], pw1, hg, NN);
        cudaStreamWaitEvent(s, evPrep[g], 0);
        agg256_kernel<<<AGG_BLKS, 256, 0, s>>>(g, hg, b1, ag);
        gemm_mma_kernel<false, 256, 128>
            <<<GB, 256, SM_L12, s>>>(ag, pw2, hg, NN);
        agg128_kernel<<<AGG_BLKS, 256, 0, s>>>(g, hg, b2, ag);
        gemm_mma_kernel<false, 128, 64>
            <<<GB, 256, SM_L3, s>>>(ag, pw3, hg, NN);
        agg3_kernel<<<AGG_BLKS, 256, 0, s>>>(g, hg, b3);

        cudaEventRecord(evJoin[g], s);
    }

    for (int g = 0; g < 3; g++) cudaStreamWaitEvent(0, evJoin[g], 0);
    final_reduce_kernel<<<1, 1024>>>(out);
}

// round 15
// speedup vs baseline: 1.1612x; 1.1612x over previous
#include <cuda_runtime.h>
#include <cuda_fp16.h>
#include <math.h>
#include <stdint.h>

#define NN 50000
#define EMAX 800000
#define AGG_BLKS 6250  // NN/8 warps-per-block

// ======================= device scratch (triplicated per graph) ==========
__device__ float g_dis[3][NN];
__device__ int   g_count[3][NN];   // zero at load; scan_block re-zeroes after use
__device__ int   g_fill[3][NN];    // set to rowptr by scan_add each run
__device__ int   g_rowptr[3][NN + 1];
__device__ int   g_bsum[3][256];
__device__ int   g_boff[3][256];
__device__ int   g_csrc[3][EMAX];
__device__ float g_cw[3][EMAX];
__device__ __half g_h[3][(size_t)NN * 256];   // GEMM output
__device__ __half g_a[3][(size_t)NN * 256];   // agg output / GEMM input
__device__ __half g_Wt1[256 * 256];           // W^T fp16 [N,K]
__device__ __half g_Wt2[128 * 256];
__device__ __half g_Wt3[64 * 128];
__device__ float g_part[3 * AGG_BLKS];        // layer-3 block partials

// ======================= PTX wrappers =======================
__device__ __forceinline__ uint32_t smem_u32(const void* p) {
    uint32_t a;
    asm("{ .reg .u64 t; cvta.to.shared.u64 t, %1; cvt.u32.u64 %0, t; }"
        : "=r"(a) : "l"(p));
    return a;
}

__device__ __forceinline__ void ldsm_x4(uint32_t* r, uint32_t addr) {
    asm volatile(
        "ldmatrix.sync.aligned.m8n8.x4.shared.b16 {%0,%1,%2,%3}, [%4];"
        : "=r"(r[0]), "=r"(r[1]), "=r"(r[2]), "=r"(r[3]) : "r"(addr));
}

__device__ __forceinline__ void mma_f16(float* d, const uint32_t* a,
                                        uint32_t b0, uint32_t b1) {
    asm volatile(
        "mma.sync.aligned.m16n8k16.row.col.f32.f16.f16.f32 "
        "{%0,%1,%2,%3}, {%4,%5,%6,%7}, {%8,%9}, {%0,%1,%2,%3};"
        : "+f"(d[0]), "+f"(d[1]), "+f"(d[2]), "+f"(d[3])
        : "r"(a[0]), "r"(a[1]), "r"(a[2]), "r"(a[3]), "r"(b0), "r"(b1));
}

__device__ __forceinline__ float2 h2f2(uint32_t u) {
    return __half22float2(*(__half2*)&u);
}
__device__ __forceinline__ uint32_t f2h2(float x, float y) {
    __half2 h = __floats2half2_rn(x, y);
    return *(uint32_t*)&h;
}

// ======================= graph-prep kernels ==============================
__global__ void count_edges_kernel(int z, const int* __restrict__ ei, int E) {
    int e = blockIdx.x * blockDim.x + threadIdx.x;
    const int* dst = ei + E;
    if (e < E) atomicAdd(&g_count[z][dst[e]], 1);
}

// reads degree, computes dis, re-zeroes g_count for the next replay
__global__ void scan_block_kernel(int z) {
    __shared__ int sd[256];
    int tid = threadIdx.x;
    int i = blockIdx.x * 256 + tid;
    int v = 0;
    if (i < NN) {
        v = g_count[z][i];
        g_count[z][i] = 0;  // restore invariant for next replay
        g_dis[z][i] = rsqrtf((float)v + 1.0f);
    }
    sd[tid] = v;
    __syncthreads();
    for (int off = 1; off < 256; off <<= 1) {
        int t = (tid >= off) ? sd[tid - off] : 0;
        __syncthreads();
        sd[tid] += t;
        __syncthreads();
    }
    if (i < NN) g_rowptr[z][i] = sd[tid] - v;
    if (tid == 255) g_bsum[z][blockIdx.x] = sd[255];
}

__global__ void scan_tops_kernel(int z, int nb) {
    __shared__ int sd[256];
    int tid = threadIdx.x;
    int v = (tid < nb) ? g_bsum[z][tid] : 0;
    sd[tid] = v;
    __syncthreads();
    for (int off = 1; off < 256; off <<= 1) {
        int t = (tid >= off) ? sd[tid - off] : 0;
        __syncthreads();
        sd[tid] += t;
        __syncthreads();
    }
    g_boff[z][tid] = sd[tid] - v;
}

// finalizes rowptr AND initializes the fill cursor g_fill = rowptr
__global__ void scan_add_kernel(int z, int E) {
    int i = blockIdx.x * 256 + threadIdx.x;
    if (i < NN) {
        int r = g_rowptr[z][i] + g_boff[z][blockIdx.x];
        g_rowptr[z][i] = r;
        g_fill[z][i] = r;
    }
    if (i == 0) g_rowptr[z][NN] = E;
}

__global__ void fill_csr_kernel(int z, const int* __restrict__ ei, int E) {
    int e = blockIdx.x * blockDim.x + threadIdx.x;
    if (e >= E) return;
    const int* src = ei;
    const int* dst = ei + E;
    int d = dst[e];
    int s = src[e];
    int pos = atomicAdd(&g_fill[z][d], 1);  // cursor pre-seeded with rowptr
    g_csrc[z][pos] = s;
    g_cw[z][pos] = g_dis[z][s] * g_dis[z][d];
}

// all three W [K,N] fp32 -> Wt [N,K] fp16 in one launch
__global__ void wt_all_kernel(const float* W1, const float* W2,
                              const float* W3) {
    int i = blockIdx.x * blockDim.x + threadIdx.x;
    if (i < 65536) {
        int nrow = i >> 8, k = i & 255;
        g_Wt1[i] = __float2half_rn(W1[k * 256 + nrow]);
    } else if (i < 98304) {
        int j = i - 65536;
        int nrow = j >> 8, k = j & 255;
        g_Wt2[j] = __float2half_rn(W2[k * 128 + nrow]);
    } else if (i < 106496) {
        int j = i - 98304;
        int nrow = j >> 7, k = j & 127;
        g_Wt3[j] = __float2half_rn(W3[k * 64 + nrow]);
    }
}

// ======================= HMMA GEMM (R11-proven: 64-col chunks, occ 2) =====
// C[n,N](fp16) = A[n,K] @ Wt^T. CTA: 128 rows; A staged once, loop over N in
// 64-col chunks restaging only W. 8 warps 4x2, warp tile 32x32.
template <bool AFP32, int K, int N>
__global__ __launch_bounds__(256) void gemm_mma_kernel(
    const void* __restrict__ Ain, const __half* __restrict__ Wt,
    __half* __restrict__ C, int n) {
    constexpr int LDS = K + 8;
    extern __shared__ __half sm[];
    __half* As = sm;               // [128][LDS]
    __half* Ws = sm + 128 * LDS;   // [64][LDS]

    int tid = threadIdx.x;
    int lane = tid & 31;
    int warp = tid >> 5;
    int rowBase = blockIdx.x * 128;
    int warpM = (warp >> 1) * 32;
    int warpN = (warp & 1) * 32;

    // ---- stage A (128 x K) once ----
    {
        constexpr int K8 = K / 8;
        for (int v = tid; v < 128 * K8; v += 256) {
            int r = v / K8;
            int k0 = (v - r * K8) * 8;
            int gr = rowBase + r;
            uint4 val = make_uint4(0, 0, 0, 0);
            if (gr < n) {
                if (AFP32) {
                    const float4* ap =
                        (const float4*)((const float*)Ain + (size_t)gr * K + k0);
                    float4 f0 = ap[0], f1 = ap[1];
                    val.x = f2h2(f0.x, f0.y);
                    val.y = f2h2(f0.z, f0.w);
                    val.z = f2h2(f1.x, f1.y);
                    val.w = f2h2(f1.z, f1.w);
                } else {
                    val = *(const uint4*)((const __half*)Ain +
                                          (size_t)gr * K + k0);
                }
            }
            *(uint4*)(As + r * LDS + k0) = val;
        }
    }
    __syncthreads();

    uint32_t sA = smem_u32(As);
    uint32_t sW = smem_u32(Ws);
    int lr = lane & 15;
    int lc = (lane >> 4) * 8;
    int groupID = lane >> 2;
    int qcol = (lane & 3) * 2;

    for (int cb = 0; cb < N / 64; cb++) {
        int colBase = cb * 64;
        if (cb) __syncthreads();
        // ---- stage W chunk (64 x K) ----
        {
            constexpr int K8 = K / 8;
            for (int v = tid; v < 64 * K8; v += 256) {
                int r = v / K8;
                int k0 = (v - r * K8) * 8;
                *(uint4*)(Ws + r * LDS + k0) =
                    *(const uint4*)(Wt + (size_t)(colBase + r) * K + k0);
            }
        }
        __syncthreads();

        float acc[2][4][4] = {};
#pragma unroll
        for (int k0 = 0; k0 < K; k0 += 16) {
            uint32_t af[2][4], bf[2][4];
#pragma unroll
            for (int mt = 0; mt < 2; mt++) {
                uint32_t addr =
                    sA + ((warpM + mt * 16 + lr) * LDS + k0 + lc) * 2;
                ldsm_x4(af[mt], addr);
            }
#pragma unroll
            for (int nh = 0; nh < 2; nh++) {
                uint32_t addr =
                    sW + ((warpN + nh * 16 + lr) * LDS + k0 + lc) * 2;
                ldsm_x4(bf[nh], addr);  // Ws is [n][k], k-contiguous
            }
#pragma unroll
            for (int mt = 0; mt < 2; mt++) {
#pragma unroll
                for (int nh = 0; nh < 2; nh++) {
                    mma_f16(acc[mt][nh * 2 + 0], af[mt], bf[nh][0], bf[nh][2]);
                    mma_f16(acc[mt][nh * 2 + 1], af[mt], bf[nh][1], bf[nh][3]);
                }
            }
        }

        // ---- epilogue ----
#pragma unroll
        for (int mt = 0; mt < 2; mt++) {
#pragma unroll
            for (int half = 0; half < 2; half++) {
                int row = rowBase + warpM + mt * 16 + groupID + half * 8;
                if (row < n) {
                    uint32_t* orow = (uint32_t*)(C + (size_t)row * N + colBase);
#pragma unroll
                    for (int nt = 0; nt < 4; nt++) {
                        orow[(warpN + nt * 8 + qcol) >> 1] =
                            f2h2(acc[mt][nt][half * 2 + 0],
                                 acc[mt][nt][half * 2 + 1]);
                    }
                }
            }
        }
    }
}

// ======================= aggregation (fp16 gather, vectorized) ============
__global__ __launch_bounds__(256) void agg256_kernel(
    int z, const __half* __restrict__ h, const float* __restrict__ bias,
    __half* __restrict__ out) {
    int warp = blockIdx.x * 8 + (threadIdx.x >> 5);
    int lane = threadIdx.x & 31;
    if (warp >= NN) return;

    float dv = g_dis[z][warp];
    float dd = dv * dv;
    float acc[8];
    {
        uint4 u = *(const uint4*)(h + (size_t)warp * 256 + lane * 8);
        float2 f0 = h2f2(u.x), f1 = h2f2(u.y), f2 = h2f2(u.z), f3 = h2f2(u.w);
        const float* bp = bias + lane * 8;
        acc[0] = f0.x * dd + bp[0]; acc[1] = f0.y * dd + bp[1];
        acc[2] = f1.x * dd + bp[2]; acc[3] = f1.y * dd + bp[3];
        acc[4] = f2.x * dd + bp[4]; acc[5] = f2.y * dd + bp[5];
        acc[6] = f3.x * dd + bp[6]; acc[7] = f3.y * dd + bp[7];
    }

    int e0 = g_rowptr[z][warp];
    int e1 = g_rowptr[z][warp + 1];
    int e = e0;
    for (; e + 1 < e1; e += 2) {
        int s0 = g_csrc[z][e], s1 = g_csrc[z][e + 1];
        float w0 = g_cw[z][e], w1 = g_cw[z][e + 1];
        uint4 u0 = __ldg((const uint4*)(h + (size_t)s0 * 256) + lane);
        uint4 u1 = __ldg((const uint4*)(h + (size_t)s1 * 256) + lane);
        float2 a0 = h2f2(u0.x), a1 = h2f2(u0.y), a2 = h2f2(u0.z), a3 = h2f2(u0.w);
        acc[0] = fmaf(w0, a0.x, acc[0]); acc[1] = fmaf(w0, a0.y, acc[1]);
        acc[2] = fmaf(w0, a1.x, acc[2]); acc[3] = fmaf(w0, a1.y, acc[3]);
        acc[4] = fmaf(w0, a2.x, acc[4]); acc[5] = fmaf(w0, a2.y, acc[5]);
        acc[6] = fmaf(w0, a3.x, acc[6]); acc[7] = fmaf(w0, a3.y, acc[7]);
        float2 b0 = h2f2(u1.x), b1 = h2f2(u1.y), b2 = h2f2(u1.z), b3 = h2f2(u1.w);
        acc[0] = fmaf(w1, b0.x, acc[0]); acc[1] = fmaf(w1, b0.y, acc[1]);
        acc[2] = fmaf(w1, b1.x, acc[2]); acc[3] = fmaf(w1, b1.y, acc[3]);
        acc[4] = fmaf(w1, b2.x, acc[4]); acc[5] = fmaf(w1, b2.y, acc[5]);
        acc[6] = fmaf(w1, b3.x, acc[6]); acc[7] = fmaf(w1, b3.y, acc[7]);
    }
    if (e < e1) {
        int s0 = g_csrc[z][e];
        float w0 = g_cw[z][e];
        uint4 u0 = __ldg((const uint4*)(h + (size_t)s0 * 256) + lane);
        float2 a0 = h2f2(u0.x), a1 = h2f2(u0.y), a2 = h2f2(u0.z), a3 = h2f2(u0.w);
        acc[0] = fmaf(w0, a0.x, acc[0]); acc[1] = fmaf(w0, a0.y, acc[1]);
        acc[2] = fmaf(w0, a1.x, acc[2]); acc[3] = fmaf(w0, a1.y, acc[3]);
        acc[4] = fmaf(w0, a2.x, acc[4]); acc[5] = fmaf(w0, a2.y, acc[5]);
        acc[6] = fmaf(w0, a3.x, acc[6]); acc[7] = fmaf(w0, a3.y, acc[7]);
    }

    uint4 o;
    o.x = f2h2(fmaxf(acc[0], 0.f), fmaxf(acc[1], 0.f));
    o.y = f2h2(fmaxf(acc[2], 0.f), fmaxf(acc[3], 0.f));
    o.z = f2h2(fmaxf(acc[4], 0.f), fmaxf(acc[5], 0.f));
    o.w = f2h2(fmaxf(acc[6], 0.f), fmaxf(acc[7], 0.f));
    *((uint4*)(out + (size_t)warp * 256) + lane) = o;
}

__global__ __launch_bounds__(256) void agg128_kernel(
    int z, const __half* __restrict__ h, const float* __restrict__ bias,
    __half* __restrict__ out) {
    int warp = blockIdx.x * 8 + (threadIdx.x >> 5);
    int lane = threadIdx.x & 31;
    if (warp >= NN) return;

    float dv = g_dis[z][warp];
    float dd = dv * dv;
    float acc[4];
    {
        uint2 u = *(const uint2*)(h + (size_t)warp * 128 + lane * 4);
        float2 f0 = h2f2(u.x), f1 = h2f2(u.y);
        const float* bp = bias + lane * 4;
        acc[0] = f0.x * dd + bp[0]; acc[1] = f0.y * dd + bp[1];
        acc[2] = f1.x * dd + bp[2]; acc[3] = f1.y * dd + bp[3];
    }

    int e0 = g_rowptr[z][warp];
    int e1 = g_rowptr[z][warp + 1];
    int e = e0;
    for (; e + 1 < e1; e += 2) {
        int s0 = g_csrc[z][e], s1 = g_csrc[z][e + 1];
        float w0 = g_cw[z][e], w1 = g_cw[z][e + 1];
        uint2 u0 = __ldg((const uint2*)(h + (size_t)s0 * 128) + lane);
        uint2 u1 = __ldg((const uint2*)(h + (size_t)s1 * 128) + lane);
        float2 a0 = h2f2(u0.x), a1 = h2f2(u0.y);
        acc[0] = fmaf(w0, a0.x, acc[0]); acc[1] = fmaf(w0, a0.y, acc[1]);
        acc[2] = fmaf(w0, a1.x, acc[2]); acc[3] = fmaf(w0, a1.y, acc[3]);
        float2 b0 = h2f2(u1.x), b1 = h2f2(u1.y);
        acc[0] = fmaf(w1, b0.x, acc[0]); acc[1] = fmaf(w1, b0.y, acc[1]);
        acc[2] = fmaf(w1, b1.x, acc[2]); acc[3] = fmaf(w1, b1.y, acc[3]);
    }
    if (e < e1) {
        int s0 = g_csrc[z][e];
        float w0 = g_cw[z][e];
        uint2 u0 = __ldg((const uint2*)(h + (size_t)s0 * 128) + lane);
        float2 a0 = h2f2(u0.x), a1 = h2f2(u0.y);
        acc[0] = fmaf(w0, a0.x, acc[0]); acc[1] = fmaf(w0, a0.y, acc[1]);
        acc[2] = fmaf(w0, a1.x, acc[2]); acc[3] = fmaf(w0, a1.y, acc[3]);
    }

    uint2 o;
    o.x = f2h2(fmaxf(acc[0], 0.f), fmaxf(acc[1], 0.f));
    o.y = f2h2(fmaxf(acc[2], 0.f), fmaxf(acc[3], 0.f));
    *((uint2*)(out + (size_t)warp * 128) + lane) = o;
}

// layer-3 agg (M=64) fused with relu + block partial sum (fp32 path)
__global__ __launch_bounds__(256) void agg3_kernel(
    int z, const __half* __restrict__ h, const float* __restrict__ bias) {
    int wlocal = threadIdx.x >> 5;
    int warp = blockIdx.x * 8 + wlocal;
    int lane = threadIdx.x & 31;

    float s = 0.0f;
    if (warp < NN) {
        float dv = g_dis[z][warp];
        float dd = dv * dv;
        uint32_t u = *((const uint32_t*)(h + (size_t)warp * 64) + lane);
        float2 f = h2f2(u);
        int c = 2 * lane;
        float a0 = f.x * dd + bias[c];
        float a1 = f.y * dd + bias[c + 1];

        int e0 = g_rowptr[z][warp];
        int e1 = g_rowptr[z][warp + 1];
        int e = e0;
        for (; e + 1 < e1; e += 2) {
            int s0 = g_csrc[z][e], s1 = g_csrc[z][e + 1];
            float w0 = g_cw[z][e], w1 = g_cw[z][e + 1];
            uint32_t u0 = __ldg((const uint32_t*)(h + (size_t)s0 * 64) + lane);
            uint32_t u1 = __ldg((const uint32_t*)(h + (size_t)s1 * 64) + lane);
            float2 fa = h2f2(u0), fb = h2f2(u1);
            a0 = fmaf(w0, fa.x, a0); a1 = fmaf(w0, fa.y, a1);
            a0 = fmaf(w1, fb.x, a0); a1 = fmaf(w1, fb.y, a1);
        }
        if (e < e1) {
            int s0 = g_csrc[z][e];
            float w0 = g_cw[z][e];
            uint32_t u0 = __ldg((const uint32_t*)(h + (size_t)s0 * 64) + lane);
            float2 fa = h2f2(u0);
            a0 = fmaf(w0, fa.x, a0); a1 = fmaf(w0, fa.y, a1);
        }
        s = fmaxf(a0, 0.0f) + fmaxf(a1, 0.0f);
    }
#pragma unroll
    for (int o = 16; o; o >>= 1) s += __shfl_down_sync(0xFFFFFFFFu, s, o);
    __shared__ float ws[8];
    if (lane == 0) ws[wlocal] = s;
    __syncthreads();
    if (threadIdx.x < 8) {
        float t = ws[threadIdx.x];
#pragma unroll
        for (int o = 4; o; o >>= 1) t += __shfl_down_sync(0xFFu, t, o);
        if (threadIdx.x == 0) g_part[z * AGG_BLKS + blockIdx.x] = t;
    }
}

__global__ void final_reduce_kernel(float* __restrict__ out) {
    float s = 0.0f;
    for (int i = threadIdx.x; i < 3 * AGG_BLKS; i += 1024) s += g_part[i];
#pragma unroll
    for (int o = 16; o; o >>= 1) s += __shfl_down_sync(0xFFFFFFFFu, s, o);
    __shared__ float ws[32];
    if ((threadIdx.x & 31) == 0) ws[threadIdx.x >> 5] = s;
    __syncthreads();
    if (threadIdx.x < 32) {
        float t = ws[threadIdx.x];
#pragma unroll
        for (int o = 16; o; o >>= 1) t += __shfl_down_sync(0xFFFFFFFFu, t, o);
        if (threadIdx.x == 0) out[0] = t * (1.0f / 64.0f);
    }
}

// ======================= launcher =======================
extern "C" void kernel_launch(void* const* d_in, const int* in_sizes, int n_in,
                              void* d_out, int out_size) {
    float* out = (float*)d_out;

    // one-time host resources: EXACTLY 3 streams (proven footprint)
    static cudaStream_t st[3];
    static cudaEvent_t evRoot, evW, evJoin[3];
    static bool inited = false;
    if (!inited) {
        inited = true;
        for (int g = 0; g < 3; g++) {
            cudaStreamCreateWithFlags(&st[g], cudaStreamNonBlocking);
            cudaEventCreateWithFlags(&evJoin[g], cudaEventDisableTiming);
        }
        cudaEventCreateWithFlags(&evRoot, cudaEventDisableTiming);
        cudaEventCreateWithFlags(&evW, cudaEventDisableTiming);
    }

    __half *ph, *pa, *pw1, *pw2, *pw3;
    cudaGetSymbolAddress((void**)&ph, g_h);
    cudaGetSymbolAddress((void**)&pa, g_a);
    cudaGetSymbolAddress((void**)&pw1, g_Wt1);
    cudaGetSymbolAddress((void**)&pw2, g_Wt2);
    cudaGetSymbolAddress((void**)&pw3, g_Wt3);

    const int SM256 = 192 * (256 + 8) * 2;  // 101376 -> 2 CTAs/SM
    const int SM128 = 192 * (128 + 8) * 2;  // 52224
    cudaFuncSetAttribute(gemm_mma_kernel<true, 256, 256>,
                         cudaFuncAttributeMaxDynamicSharedMemorySize, SM256);
    cudaFuncSetAttribute(gemm_mma_kernel<false, 256, 128>,
                         cudaFuncAttributeMaxDynamicSharedMemorySize, SM256);
    cudaFuncSetAttribute(gemm_mma_kernel<false, 128, 64>,
                         cudaFuncAttributeMaxDynamicSharedMemorySize, SM128);

    const int NB = (NN + 255) / 256;  // 196
    const int GB = (NN + 127) / 128;  // 391

    const float* b1 = (const float*)d_in[7];
    const float* b2 = (const float*)d_in[9];
    const float* b3 = (const float*)d_in[11];

    // root fork first: preps don't need weights
    cudaEventRecord(evRoot, 0);
    wt_all_kernel<<<(106496 + 255) / 256, 256>>>(
        (const float*)d_in[6], (const float*)d_in[8], (const float*)d_in[10]);
    cudaEventRecord(evW, 0);

    for (int g = 0; g < 3; g++) {
        const int* ei = (const int*)d_in[3 + g];
        int E = in_sizes[3 + g] / 2;
        int EB = (E + 255) / 256;
        __half* hg = ph + (size_t)g * NN * 256;
        __half* ag = pa + (size_t)g * NN * 256;
        cudaStream_t s = st[g];

        // prep chain (waits only evRoot; overlaps wt_all)
        cudaStreamWaitEvent(s, evRoot, 0);
        count_edges_kernel<<<EB, 256, 0, s>>>(g, ei, E);
        scan_block_kernel<<<NB, 256, 0, s>>>(g);
        scan_tops_kernel<<<1, 256, 0, s>>>(g, NB);
        scan_add_kernel<<<NB, 256, 0, s>>>(g, E);
        fill_csr_kernel<<<EB, 256, 0, s>>>(g, ei, E);

        // compute chain (gemm1 additionally waits weights)
        cudaStreamWaitEvent(s, evW, 0);
        gemm_mma_kernel<true, 256, 256>
            <<<GB, 256, SM256, s>>>(d_in[g], pw1, hg, NN);
        agg256_kernel<<<AGG_BLKS, 256, 0, s>>>(g, hg, b1, ag);
        gemm_mma_kernel<false, 256, 128>
            <<<GB, 256, SM256, s>>>(ag, pw2, hg, NN);
        agg128_kernel<<<AGG_BLKS, 256, 0, s>>>(g, hg, b2, ag);
        gemm_mma_kernel<false, 128, 64>
            <<<GB, 256, SM128, s>>>(ag, pw3, hg, NN);
        agg3_kernel<<<AGG_BLKS, 256, 0, s>>>(g, hg, b3);

        cudaEventRecord(evJoin[g], s);
    }

    for (int g = 0; g < 3; g++) cudaStreamWaitEvent(0, evJoin[g], 0);
    final_reduce_kernel<<<1, 1024>>>(out);
}